// round 17
// baseline (speedup 1.0000x reference)
#include <cuda_runtime.h>
#include <cstdint>

#define NB      128
#define CG      2              // block-columns per CTA
#define GROUPS  (NB / CG)      // 64
#define GCOLS   (CG * 32)      // 64
#define NTHR    128            // 4 warps, each owns 32 rows (2 m16 tiles)
#define MAXL    160
#define N_DIM   4096
#define BATCH   1024
#define NBLKS   4096

// A fragments: g_xa[((rb*128 + cib)*4 + kt)*32 + lane] = float4 {a0,a1,a2,a3}
//   rb = row-block (16 rows) 0..63, a0=(rb*16+l>>2, cib*32+kt*8+(l&3)),
//   a1=+8 rows, a2=+4 cols, a3=+8r+4c.  16 MB, tf32-rounded.
__device__ float4 g_xa[64 * NB * 4 * 32];
// B fragments: g_bf[((n*4 + kt)*4 + nt)*32 + lane] = float2 {b0,b1}
//   b0 = B[kt*8+(l&3)][nt*8+(l>>2)], b1 = +4 k-rows.  16 MB, tf32-rounded.
__device__ float2 g_bf[NBLKS * 16 * 32];

// ---------------- helpers ----------------

// cvt.rna.tf32.f32 requires a .b32 destination register -> "=r"
__device__ __forceinline__ uint32_t tf32b(float a) {
    uint32_t r;
    asm("cvt.rna.tf32.f32 %0, %1;" : "=r"(r) : "f"(a));
    return r;
}

#define MMA_TF32(C, A0, A1, A2, A3, B0, B1)                                       \
    asm volatile("mma.sync.aligned.m16n8k8.row.col.f32.tf32.tf32.f32 "            \
                 "{%0,%1,%2,%3},{%4,%5,%6,%7},{%8,%9},{%0,%1,%2,%3};"             \
                 : "+f"((C)[0]), "+f"((C)[1]), "+f"((C)[2]), "+f"((C)[3])         \
                 : "r"(A0), "r"(A1), "r"(A2), "r"(A3), "r"(B0), "r"(B1))

// ---------------- prep kernels ----------------

// x -> A-fragment layout (tf32). One float4 (one lane's frag) per thread.
__global__ void convert_xa_kernel(const float* __restrict__ x) {
    int idx  = blockIdx.x * 256 + threadIdx.x;   // 0 .. 64*128*4*32-1 (1M)
    int lane = idx & 31;
    int kt   = (idx >> 5) & 3;
    int cib  = (idx >> 7) & 127;
    int rb   = idx >> 14;
    int row  = rb * 16 + (lane >> 2);
    int col  = cib * 32 + kt * 8 + (lane & 3);
    const float* xr = x + (size_t)row * N_DIM;
    float4 v;
    v.x = __uint_as_float(tf32b(xr[col]));
    v.y = __uint_as_float(tf32b(xr[col + 8 * N_DIM]));
    v.z = __uint_as_float(tf32b(xr[col + 4]));
    v.w = __uint_as_float(tf32b(xr[col + 4 + 8 * N_DIM]));
    g_xa[idx] = v;
}

// kern -> B-fragment layout (tf32). One float2 per thread.
__global__ void convert_bf_kernel(const float* __restrict__ kern) {
    int idx  = blockIdx.x * 256 + threadIdx.x;   // 0 .. NBLKS*16*32-1 (2M)
    int lane = idx & 31;
    int nt   = (idx >> 5) & 3;
    int kt   = (idx >> 7) & 3;
    int n    = idx >> 9;
    int k    = kt * 8 + (lane & 3);
    int col  = nt * 8 + (lane >> 2);
    const float* kb = kern + (size_t)n * 1024;
    float2 v;
    v.x = __uint_as_float(tf32b(kb[k * 32 + col]));
    v.y = __uint_as_float(tf32b(kb[(k + 4) * 32 + col]));
    g_bf[idx] = v;
}

// ---------------- work lists ----------------
// entry: n[0:12) | cib[12:19) | lco[19:20); list preserves sorted (ci,co) order.

__device__ int g_cnt[GROUPS];
__device__ int g_list[GROUPS * MAXL];

#define LTHR 256
__global__ void build_lists_kernel(const int* __restrict__ ci, const int* __restrict__ co) {
    __shared__ int pref[LTHR];
    const int g = blockIdx.x;
    const int t = threadIdx.x;
    const int base = t * (NBLKS / LTHR);   // 16 entries per thread
    int cnt = 0;
#pragma unroll
    for (int j = 0; j < NBLKS / LTHR; j++)
        if ((co[base + j] >> 1) == g) cnt++;
    pref[t] = cnt;
    __syncthreads();
    for (int off = 1; off < LTHR; off <<= 1) {
        int v = (t >= off) ? pref[t - off] : 0;
        __syncthreads();
        pref[t] += v;
        __syncthreads();
    }
    int pos = pref[t] - cnt;
#pragma unroll
    for (int j = 0; j < NBLKS / LTHR; j++) {
        int n = base + j;
        int c = co[n];
        if ((c >> 1) == g) {
            g_list[g * MAXL + pos] = n | (ci[n] << 12) | ((c & 1) << 19);
            pos++;
        }
    }
    if (t == LTHR - 1) g_cnt[g] = pref[LTHR - 1];
}

// ---------------- main kernel ----------------
// Register-double-buffered fragment streaming: at iter i, issue LDGs for
// block i+1 (B always; A on cib change into alternate buffer), then run
// block i's MMAs on resident fragments. No datapath SMEM, no barriers.

__global__ void __launch_bounds__(NTHR, 2)
bs_mma_kernel(const float* __restrict__ bias, float* __restrict__ out) {
    __shared__ int   list_s[MAXL];
    __shared__ float bias_s[GCOLS];

    const int g   = blockIdx.x;    // column group 0..63 (64 cols)
    const int by  = blockIdx.y;    // batch tile 0..7 (128 rows)
    const int tid = threadIdx.x;
    const int w   = tid >> 5;      // 0..3
    const int lane = tid & 31;
    const int kq  = lane & 3;
    const int nq  = lane >> 2;

    const int cnt = g_cnt[g];
    for (int j = tid; j < cnt; j += NTHR) list_s[j] = g_list[g * MAXL + j];
    if (tid < GCOLS) bias_s[tid] = bias[g * GCOLS + tid];
    __syncthreads();

    float acc[2][8][4];
#pragma unroll
    for (int m = 0; m < 2; m++)
#pragma unroll
        for (int i = 0; i < 8; i++)
#pragma unroll
            for (int j = 0; j < 4; j++) acc[m][i][j] = 0.f;

    // row-blocks for this warp's two m16 tiles
    const int rb0 = by * 8 + 2 * w;

    uint32_t afr[2][2][4][4];      // [abuf][m][kt][reg]
    uint32_t bfr[2][4][4][2];      // [bbuf][kt][nt][reg]

    auto load_a = [&](uint32_t (&dst)[2][4][4], int cib) {
#pragma unroll
        for (int m = 0; m < 2; m++) {
            const float4* ap = g_xa + (size_t)((rb0 + m) * 128 + cib) * 128 + lane;
#pragma unroll
            for (int kt = 0; kt < 4; kt++) {
                float4 v = ap[kt * 32];
                dst[m][kt][0] = __float_as_uint(v.x);
                dst[m][kt][1] = __float_as_uint(v.y);
                dst[m][kt][2] = __float_as_uint(v.z);
                dst[m][kt][3] = __float_as_uint(v.w);
            }
        }
    };
    auto load_b = [&](uint32_t (&dst)[4][4][2], int n) {
        const float2* bp = g_bf + (size_t)n * 512 + lane;
#pragma unroll
        for (int kt = 0; kt < 4; kt++)
#pragma unroll
            for (int nt = 0; nt < 4; nt++) {
                float2 v = bp[(kt * 4 + nt) * 32];
                dst[kt][nt][0] = __float_as_uint(v.x);
                dst[kt][nt][1] = __float_as_uint(v.y);
            }
    };

    if (cnt > 0) {
        int v0 = list_s[0];
        load_a(afr[0], (v0 >> 12) & 127);
        load_b(bfr[0], v0 & 0xFFF);
        int ab = 0;

        for (int i = 0; i < cnt; i++) {
            int vi   = list_s[i];
            int lco  = (vi >> 19) & 1;
            int cib_i = (vi >> 12) & 127;
            int bb   = i & 1;

            // prefetch block i+1 into alternate buffers (overlaps MMAs below)
            int abn = ab;
            if (i + 1 < cnt) {
                int v1 = list_s[i + 1];
                load_b(bfr[bb ^ 1], v1 & 0xFFF);
                int cib1 = (v1 >> 12) & 127;
                if (cib1 != cib_i) {
                    abn = ab ^ 1;
                    load_a(afr[abn], cib1);
                }
            }

            if (lco) {
#pragma unroll
                for (int kt = 0; kt < 4; kt++)
#pragma unroll
                    for (int nt = 0; nt < 4; nt++) {
                        MMA_TF32(acc[0][4 + nt], afr[ab][0][kt][0], afr[ab][0][kt][1],
                                 afr[ab][0][kt][2], afr[ab][0][kt][3],
                                 bfr[bb][kt][nt][0], bfr[bb][kt][nt][1]);
                        MMA_TF32(acc[1][4 + nt], afr[ab][1][kt][0], afr[ab][1][kt][1],
                                 afr[ab][1][kt][2], afr[ab][1][kt][3],
                                 bfr[bb][kt][nt][0], bfr[bb][kt][nt][1]);
                    }
            } else {
#pragma unroll
                for (int kt = 0; kt < 4; kt++)
#pragma unroll
                    for (int nt = 0; nt < 4; nt++) {
                        MMA_TF32(acc[0][nt], afr[ab][0][kt][0], afr[ab][0][kt][1],
                                 afr[ab][0][kt][2], afr[ab][0][kt][3],
                                 bfr[bb][kt][nt][0], bfr[bb][kt][nt][1]);
                        MMA_TF32(acc[1][nt], afr[ab][1][kt][0], afr[ab][1][kt][1],
                                 afr[ab][1][kt][2], afr[ab][1][kt][3],
                                 bfr[bb][kt][nt][0], bfr[bb][kt][nt][1]);
                    }
            }
            ab = abn;
        }
    }

    // ---- epilogue: bias + relu ----
    // C frag m16n8: c0,c1 -> (row=nq, col=2kq), c2,c3 -> (row=nq+8, col=2kq)
#pragma unroll
    for (int m = 0; m < 2; m++) {
        int r = by * 128 + 32 * w + 16 * m + nq;
        size_t rbase0 = (size_t)r * N_DIM + g * GCOLS;
        size_t rbase1 = rbase0 + 8 * (size_t)N_DIM;
#pragma unroll
        for (int nt = 0; nt < 8; nt++) {
            int c = nt * 8 + 2 * kq;
            float b0 = bias_s[c], b1 = bias_s[c + 1];
            float2 v0, v1;
            v0.x = fmaxf(acc[m][nt][0] + b0, 0.f);
            v0.y = fmaxf(acc[m][nt][1] + b1, 0.f);
            v1.x = fmaxf(acc[m][nt][2] + b0, 0.f);
            v1.y = fmaxf(acc[m][nt][3] + b1, 0.f);
            *(float2*)(out + rbase0 + c) = v0;
            *(float2*)(out + rbase1 + c) = v1;
        }
    }
}

extern "C" void kernel_launch(void* const* d_in, const int* in_sizes, int n_in,
                              void* d_out, int out_size) {
    const float* x    = (const float*)d_in[0];
    const float* kern = (const float*)d_in[1];
    const float* bias = (const float*)d_in[2];
    const int*   ci   = (const int*)d_in[3];
    const int*   co   = (const int*)d_in[4];
    float* out = (float*)d_out;

    convert_xa_kernel<<<64 * NB * 4 * 32 / 256, 256>>>(x);
    convert_bf_kernel<<<NBLKS * 16 * 32 / 256, 256>>>(kern);
    build_lists_kernel<<<GROUPS, LTHR>>>(ci, co);
    dim3 grid(GROUPS, BATCH / 128);
    bs_mma_kernel<<<grid, NTHR>>>(bias, out);
}